// round 11
// baseline (speedup 1.0000x reference)
#include <cuda_runtime.h>

// FlowComposite: flows [B,T,2,H,W] fp32 -> out [B,2,H,W] fp32.
// R11: R10's bit-exact core (scalar LDG.32 gathers -- measured cheapest
// divergent addressing mode; exact coherent t=0; reference rounding order
// px=(x+u)-0.5; exact validity-fold weights) with:
//   - 64x8 tile / 512-thread blocks (more vertical line reuse per L1; L2%
//     31.6 -> expected ~27; fewer blocks)
//   - explicit max-L1 carveout (smem=0 kernel; reclaim any smem carveout
//     for L1 to cut miss-path replays on the jittered gather window)
// HBM traffic is already exactly compulsory (2.38 TB/s measured = 434MB/dur);
// all remaining time is L1tex gather wavefronts (94.9% busy).

static constexpr int Bc = 8;
static constexpr int Tc = 12;
static constexpr int Hc = 544;
static constexpr int Wc = 960;
static constexpr int HW = Hc * Wc;

__global__ __launch_bounds__(512)
void flow_composite_kernel(const float* __restrict__ flows, float* __restrict__ out) {
    // 64x8 pixel tile per block; warp = 32 contiguous x (128B-aligned base).
    // warp&1 -> x half, warp>>1 -> row within tile.
    const int lane = threadIdx.x & 31;
    const int warp = threadIdx.x >> 5;
    const int x = (blockIdx.x << 6) + ((warp & 1) << 5) + lane;
    const int y = (blockIdx.y << 3) + (warp >> 1);
    const int b = blockIdx.z;

    const float xf = (float)x;
    const float yf = (float)y;

    const float* fb = flows + (unsigned)b * (Tc * 2 * HW);

    // ---- t = 0: u=v=0 exactly -> px = x-0.5 -> weights exactly 0.25*valid,
    // corners (x-1,x)x(y-1,y): fully coherent loads.
    float u, v;
    {
        const float* f0 = fb;
        const float* f1 = fb + HW;

        const int xm = max(x - 1, 0);
        const int ym = max(y - 1, 0);
        const int r0 = ym * Wc;
        const int r1 = y * Wc;

        const float vx = (x >= 1) ? 1.0f : 0.0f;
        const float vy = (y >= 1) ? 1.0f : 0.0f;
        const float w00 = 0.25f * (vx * vy);
        const float w10 = 0.25f * vy;
        const float w01 = 0.25f * vx;
        const float w11 = 0.25f;

        const float a00 = __ldg(f0 + r0 + xm);
        const float a10 = __ldg(f0 + r0 + x);
        const float a01 = __ldg(f0 + r1 + xm);
        const float a11 = __ldg(f0 + r1 + x);
        const float b00 = __ldg(f1 + r0 + xm);
        const float b10 = __ldg(f1 + r0 + x);
        const float b01 = __ldg(f1 + r1 + xm);
        const float b11 = __ldg(f1 + r1 + x);

        u = ((w00 * a00 + w10 * a10) + w01 * a01) + w11 * a11;
        v = ((w00 * b00 + w10 * b10) + w01 * b01) + w11 * b11;
    }

    // ---- t = 1..11: divergent scalar gathers, reference rounding order.
    #pragma unroll
    for (int t = 1; t < Tc; ++t) {
        const float* f0 = fb + (unsigned)t * (2 * HW);   // u plane
        const float* f1 = f0 + HW;                       // v plane

        // Reference order: (x + u) - 0.5 (do NOT hoist the -0.5).
        const float px = (xf + u) - 0.5f;
        const float py = (yf + v) - 0.5f;

        const int x0 = __float2int_rd(px);
        const int y0 = __float2int_rd(py);

        const float wx1 = px - (float)x0;
        const float wy1 = py - (float)y0;
        const float wx0 = 1.0f - wx1;
        const float wy0 = 1.0f - wy1;

        // Fold validity into axis weights (exact: x1.0 / x0.0).
        const float gx0 = ((x0 >= 0)  && (x0 <= Wc - 1)) ? wx0 : 0.0f;
        const float gx1 = ((x0 >= -1) && (x0 <= Wc - 2)) ? wx1 : 0.0f;
        const float gy0 = ((y0 >= 0)  && (y0 <= Hc - 1)) ? wy0 : 0.0f;
        const float gy1 = ((y0 >= -1) && (y0 <= Hc - 2)) ? wy1 : 0.0f;

        const float w00 = gx0 * gy0;
        const float w10 = gx1 * gy0;
        const float w01 = gx0 * gy1;
        const float w11 = gx1 * gy1;

        const int xc0 = min(max(x0, 0), Wc - 1);
        const int xc1 = min(max(x0 + 1, 0), Wc - 1);
        const int yc0 = min(max(y0, 0), Hc - 1);
        const int yc1 = min(max(y0 + 1, 0), Hc - 1);

        const int r0 = yc0 * Wc;
        const int r1 = yc1 * Wc;
        const int i00 = r0 + xc0;
        const int i10 = r0 + xc1;
        const int i01 = r1 + xc0;
        const int i11 = r1 + xc1;

        // 8 independent scalar gathers -> MLP 8.
        const float a00 = __ldg(f0 + i00);
        const float a10 = __ldg(f0 + i10);
        const float a01 = __ldg(f0 + i01);
        const float a11 = __ldg(f0 + i11);
        const float b00 = __ldg(f1 + i00);
        const float b10 = __ldg(f1 + i10);
        const float b01 = __ldg(f1 + i01);
        const float b11 = __ldg(f1 + i11);

        // Same summation order as reference: ((c00 + c10) + c01) + c11
        const float s0 = ((w00 * a00 + w10 * a10) + w01 * a01) + w11 * a11;
        const float s1 = ((w00 * b00 + w10 * b10) + w01 * b01) + w11 * b11;

        u += s0;
        v += s1;
    }

    const int p = y * Wc + x;
    float* ob = out + (unsigned)b * (2 * HW);
    ob[p]      = u;
    ob[HW + p] = v;
}

extern "C" void kernel_launch(void* const* d_in, const int* in_sizes, int n_in,
                              void* d_out, int out_size) {
    const float* flows = (const float*)d_in[0];
    float* out = (float*)d_out;

    // smem=0 kernel: reclaim the full unified cache for L1 (idempotent host
    // attribute set; not a stream op, graph-capture safe).
    cudaFuncSetAttribute(flow_composite_kernel,
                         cudaFuncAttributePreferredSharedMemoryCarveout, 0);

    dim3 grid(Wc / 64, Hc / 8, Bc);   // 15 x 68 x 8, exact cover
    dim3 block(512);
    flow_composite_kernel<<<grid, block>>>(flows, out);
}

// round 12
// speedup vs baseline: 1.0002x; 1.0002x over previous
#include <cuda_runtime.h>

// FlowComposite: flows [B,T,2,H,W] fp32 -> out [B,2,H,W] fp32.
// R12 FINAL: best-measured config. Scalar LDG.32 gathers (measured cheapest
// divergent addressing mode on sm_103a: .64/.128 merges lose to per-request
// return-bandwidth floors; shuffle/thread-pair sharing lose to chain
// decorrelation under iid flows). Exact coherent t=0 case; reference
// rounding order px=(x+u)-0.5 (hoisting perturbs rounding -> ~1e3x chain
// amplification); exact validity-fold weights. 32x8 tile / 256 threads
// (best harness time), max-L1 carveout (smem=0 kernel).
// Roofline: DRAM at exactly compulsory traffic (2.37 TB/s); L1tex gather
// wavefronts ~95% busy = the data-dependent floor.

static constexpr int Bc = 8;
static constexpr int Tc = 12;
static constexpr int Hc = 544;
static constexpr int Wc = 960;
static constexpr int HW = Hc * Wc;

__global__ __launch_bounds__(256)
void flow_composite_kernel(const float* __restrict__ flows, float* __restrict__ out) {
    // 32x8 pixel tile per block; warp = 32 contiguous x (128B-aligned base).
    const int x = (blockIdx.x << 5) + (threadIdx.x & 31);
    const int y = (blockIdx.y << 3) + (threadIdx.x >> 5);
    const int b = blockIdx.z;

    const float xf = (float)x;
    const float yf = (float)y;

    const float* fb = flows + (unsigned)b * (Tc * 2 * HW);

    // ---- t = 0: u=v=0 exactly -> px = x-0.5 -> weights exactly 0.25*valid,
    // corners (x-1,x)x(y-1,y): fully coherent loads.
    float u, v;
    {
        const float* f0 = fb;
        const float* f1 = fb + HW;

        const int xm = max(x - 1, 0);
        const int ym = max(y - 1, 0);
        const int r0 = ym * Wc;
        const int r1 = y * Wc;

        const float vx = (x >= 1) ? 1.0f : 0.0f;
        const float vy = (y >= 1) ? 1.0f : 0.0f;
        const float w00 = 0.25f * (vx * vy);
        const float w10 = 0.25f * vy;
        const float w01 = 0.25f * vx;
        const float w11 = 0.25f;

        const float a00 = __ldg(f0 + r0 + xm);
        const float a10 = __ldg(f0 + r0 + x);
        const float a01 = __ldg(f0 + r1 + xm);
        const float a11 = __ldg(f0 + r1 + x);
        const float b00 = __ldg(f1 + r0 + xm);
        const float b10 = __ldg(f1 + r0 + x);
        const float b01 = __ldg(f1 + r1 + xm);
        const float b11 = __ldg(f1 + r1 + x);

        u = ((w00 * a00 + w10 * a10) + w01 * a01) + w11 * a11;
        v = ((w00 * b00 + w10 * b10) + w01 * b01) + w11 * b11;
    }

    // ---- t = 1..11: divergent scalar gathers, reference rounding order.
    #pragma unroll
    for (int t = 1; t < Tc; ++t) {
        const float* f0 = fb + (unsigned)t * (2 * HW);   // u plane
        const float* f1 = f0 + HW;                       // v plane

        // Reference order: (x + u) - 0.5 (do NOT hoist the -0.5).
        const float px = (xf + u) - 0.5f;
        const float py = (yf + v) - 0.5f;

        const int x0 = __float2int_rd(px);
        const int y0 = __float2int_rd(py);

        const float wx1 = px - (float)x0;
        const float wy1 = py - (float)y0;
        const float wx0 = 1.0f - wx1;
        const float wy0 = 1.0f - wy1;

        // Fold validity into axis weights (exact: x1.0 / x0.0).
        const float gx0 = ((x0 >= 0)  && (x0 <= Wc - 1)) ? wx0 : 0.0f;
        const float gx1 = ((x0 >= -1) && (x0 <= Wc - 2)) ? wx1 : 0.0f;
        const float gy0 = ((y0 >= 0)  && (y0 <= Hc - 1)) ? wy0 : 0.0f;
        const float gy1 = ((y0 >= -1) && (y0 <= Hc - 2)) ? wy1 : 0.0f;

        const float w00 = gx0 * gy0;
        const float w10 = gx1 * gy0;
        const float w01 = gx0 * gy1;
        const float w11 = gx1 * gy1;

        const int xc0 = min(max(x0, 0), Wc - 1);
        const int xc1 = min(max(x0 + 1, 0), Wc - 1);
        const int yc0 = min(max(y0, 0), Hc - 1);
        const int yc1 = min(max(y0 + 1, 0), Hc - 1);

        const int r0 = yc0 * Wc;
        const int r1 = yc1 * Wc;
        const int i00 = r0 + xc0;
        const int i10 = r0 + xc1;
        const int i01 = r1 + xc0;
        const int i11 = r1 + xc1;

        // 8 independent scalar gathers -> MLP 8.
        const float a00 = __ldg(f0 + i00);
        const float a10 = __ldg(f0 + i10);
        const float a01 = __ldg(f0 + i01);
        const float a11 = __ldg(f0 + i11);
        const float b00 = __ldg(f1 + i00);
        const float b10 = __ldg(f1 + i10);
        const float b01 = __ldg(f1 + i01);
        const float b11 = __ldg(f1 + i11);

        // Same summation order as reference: ((c00 + c10) + c01) + c11
        const float s0 = ((w00 * a00 + w10 * a10) + w01 * a01) + w11 * a11;
        const float s1 = ((w00 * b00 + w10 * b10) + w01 * b01) + w11 * b11;

        u += s0;
        v += s1;
    }

    const int p = y * Wc + x;
    float* ob = out + (unsigned)b * (2 * HW);
    ob[p]      = u;
    ob[HW + p] = v;
}

extern "C" void kernel_launch(void* const* d_in, const int* in_sizes, int n_in,
                              void* d_out, int out_size) {
    const float* flows = (const float*)d_in[0];
    float* out = (float*)d_out;

    // smem=0 kernel: reclaim the full unified cache for L1 (idempotent host
    // attribute set; not a stream op, graph-capture safe).
    cudaFuncSetAttribute(flow_composite_kernel,
                         cudaFuncAttributePreferredSharedMemoryCarveout, 0);

    dim3 grid(Wc / 32, Hc / 8, Bc);   // 30 x 68 x 8, exact cover
    dim3 block(256);
    flow_composite_kernel<<<grid, block>>>(flows, out);
}